// round 4
// baseline (speedup 1.0000x reference)
#include <cuda_runtime.h>
#include <math.h>

#define N_NODES 4096
#define F_IN 512
#define H_HEADS 8
#define C_OUT 128
#define HC (H_HEADS * C_OUT)   // 1024
#define ALPHA 0.2f

// Scratch (allocation-free rule: __device__ globals)
__device__ float g_feats[N_NODES * HC];       // [n][h*128+c], 16 MB
__device__ float g_sself[H_HEADS * N_NODES];  // [h][n]
__device__ float g_sneigh[H_HEADS * N_NODES]; // [h][n]

// ---------------------------------------------------------------------------
// GEMM: feats[m][h*128+c] = sum_f X[m][f] * W[h][f][c]
// grid (8, 32) = (head, m-tile). 128x128 tile, BK=8, 256 threads, 8x8 microtile.
// BN=128 == C_OUT, so each block's B tile is exactly one head's W slice:
// contiguous 128-float rows -> float4 loads.
// ---------------------------------------------------------------------------
__global__ __launch_bounds__(256) void gemm_kernel(const float* __restrict__ X,
                                                   const float* __restrict__ W) {
    __shared__ float As[8][128];  // [k][m]
    __shared__ float Bs[8][128];  // [k][c]

    const int h  = blockIdx.x;
    const int m0 = blockIdx.y * 128;
    const float* Wh = W + (size_t)h * F_IN * C_OUT;

    const int t  = threadIdx.x;
    const int tx = t & 15;   // col group
    const int ty = t >> 4;   // row group

    float acc[8][8];
#pragma unroll
    for (int i = 0; i < 8; i++)
#pragma unroll
        for (int j = 0; j < 8; j++) acc[i][j] = 0.0f;

    const int arow  = t >> 1;        // 0..127
    const int acol4 = (t & 1) * 4;   // 0 or 4
    const int brow  = t >> 5;        // 0..7
    const int bcol4 = (t & 31) * 4;  // 0..124

    for (int k0 = 0; k0 < F_IN; k0 += 8) {
        float4 av = *reinterpret_cast<const float4*>(X + (size_t)(m0 + arow) * F_IN + k0 + acol4);
        float4 bv = *reinterpret_cast<const float4*>(Wh + (size_t)(k0 + brow) * C_OUT + bcol4);
        __syncthreads();  // previous iter's smem reads done
        As[acol4 + 0][arow] = av.x;
        As[acol4 + 1][arow] = av.y;
        As[acol4 + 2][arow] = av.z;
        As[acol4 + 3][arow] = av.w;
        *reinterpret_cast<float4*>(&Bs[brow][bcol4]) = bv;
        __syncthreads();

#pragma unroll
        for (int k = 0; k < 8; k++) {
            float a[8], b[8];
            float4 a0 = *reinterpret_cast<const float4*>(&As[k][ty * 8]);
            float4 a1 = *reinterpret_cast<const float4*>(&As[k][ty * 8 + 4]);
            float4 b0 = *reinterpret_cast<const float4*>(&Bs[k][tx * 8]);
            float4 b1 = *reinterpret_cast<const float4*>(&Bs[k][tx * 8 + 4]);
            a[0]=a0.x; a[1]=a0.y; a[2]=a0.z; a[3]=a0.w; a[4]=a1.x; a[5]=a1.y; a[6]=a1.z; a[7]=a1.w;
            b[0]=b0.x; b[1]=b0.y; b[2]=b0.z; b[3]=b0.w; b[4]=b1.x; b[5]=b1.y; b[6]=b1.z; b[7]=b1.w;
#pragma unroll
            for (int i = 0; i < 8; i++)
#pragma unroll
                for (int j = 0; j < 8; j++) acc[i][j] = fmaf(a[i], b[j], acc[i][j]);
        }
    }

    // write out: feats[(m0 + ty*8 + i)][h*128 + tx*8 + j]
#pragma unroll
    for (int i = 0; i < 8; i++) {
        float* dst = g_feats + (size_t)(m0 + ty * 8 + i) * HC + h * C_OUT + tx * 8;
        float4 v0 = make_float4(acc[i][0], acc[i][1], acc[i][2], acc[i][3]);
        float4 v1 = make_float4(acc[i][4], acc[i][5], acc[i][6], acc[i][7]);
        *reinterpret_cast<float4*>(dst)     = v0;
        *reinterpret_cast<float4*>(dst + 4) = v1;
    }
}

// ---------------------------------------------------------------------------
// Scores: s_self[h][n] = feats[n][h,:] . a_self[h,:]   (same for a_neigh)
// grid 4096 (one row), 256 threads (8 warps = 8 heads)
// ---------------------------------------------------------------------------
__global__ __launch_bounds__(256) void score_kernel(const float* __restrict__ a_self,
                                                    const float* __restrict__ a_neigh) {
    const int n = blockIdx.x;
    const int h = threadIdx.x >> 5;
    const int lane = threadIdx.x & 31;
    const float* frow = g_feats + (size_t)n * HC + h * C_OUT;
    float ss = 0.0f, sn = 0.0f;
#pragma unroll
    for (int c = lane; c < C_OUT; c += 32) {
        float f = frow[c];
        ss = fmaf(f, a_self[h * C_OUT + c], ss);
        sn = fmaf(f, a_neigh[h * C_OUT + c], sn);
    }
#pragma unroll
    for (int o = 16; o > 0; o >>= 1) {
        ss += __shfl_xor_sync(0xffffffffu, ss, o);
        sn += __shfl_xor_sync(0xffffffffu, sn, o);
    }
    if (lane == 0) {
        g_sself[h * N_NODES + n]  = ss;
        g_sneigh[h * N_NODES + n] = sn;
    }
}

// ---------------------------------------------------------------------------
// Aggregation: one CTA per row i.
//  1) deterministic ordered compaction of A[i,:] -> neighbor list (smem)
//  2) per-head (per-warp) softmax stats M, 1/Z over neighbors
//  3) chunked coef computation + float4 gather-accumulate of feats rows
// ---------------------------------------------------------------------------
__global__ __launch_bounds__(256) void agg_kernel(const float* __restrict__ A,
                                                  const float* __restrict__ bias,
                                                  float* __restrict__ out) {
    __shared__ int   nbr[N_NODES];
    __shared__ int   warp_cnt[8];
    __shared__ int   s_base;
    __shared__ float sM[H_HEADS], sInvZ[H_HEADS], sS[H_HEADS];
    __shared__ float coef[32][H_HEADS];

    const int i = blockIdx.x;
    const int t = threadIdx.x;
    const int lane = t & 31;
    const int w = t >> 5;

    const float* Arow = A + (size_t)i * N_NODES;

    if (t == 0) s_base = 0;
    __syncthreads();

    // ---- 1) ordered compaction (deterministic) ----
    for (int c0 = 0; c0 < N_NODES; c0 += 256) {
        const int col = c0 + t;
        const bool p = (Arow[col] != 0.0f);
        const unsigned bal = __ballot_sync(0xffffffffu, p);
        if (lane == 0) warp_cnt[w] = __popc(bal);
        __syncthreads();
        int woff = 0;
#pragma unroll
        for (int ww = 0; ww < 8; ww++)
            if (ww < w) woff += warp_cnt[ww];
        const int lpre = __popc(bal & ((1u << lane) - 1u));
        if (p) nbr[s_base + woff + lpre] = col;
        __syncthreads();
        if (t == 0) {
            int tot = 0;
#pragma unroll
            for (int ww = 0; ww < 8; ww++) tot += warp_cnt[ww];
            s_base += tot;
        }
        __syncthreads();
    }
    const int deg = s_base;  // >= 1 (self loop)

    // ---- 2) per-head softmax stats; warp w handles head w ----
    {
        const float ss = g_sself[w * N_NODES + i];
        float mx = -INFINITY;
        for (int k = lane; k < deg; k += 32)
            mx = fmaxf(mx, g_sneigh[w * N_NODES + nbr[k]]);
#pragma unroll
        for (int o = 16; o > 0; o >>= 1)
            mx = fmaxf(mx, __shfl_xor_sync(0xffffffffu, mx, o));
        float e = ss + mx;
        const float Mlogit = (e > 0.0f) ? e : ALPHA * e;  // leaky monotone -> true max logit

        float Z = 0.0f;
        for (int k = lane; k < deg; k += 32) {
            float x = ss + g_sneigh[w * N_NODES + nbr[k]];
            x = (x > 0.0f) ? x : ALPHA * x;
            Z += expf(x - Mlogit);
        }
#pragma unroll
        for (int o = 16; o > 0; o >>= 1)
            Z += __shfl_xor_sync(0xffffffffu, Z, o);
        if (lane == 0) {
            sM[w] = Mlogit;
            sInvZ[w] = 1.0f / Z;
            sS[w] = ss;
        }
    }
    __syncthreads();

    // ---- 3) gather-accumulate ----
    const int myh = t >> 5;  // cols 4t..4t+3 all lie in head t/32
    float4 acc = make_float4(0.0f, 0.0f, 0.0f, 0.0f);

    for (int k0 = 0; k0 < deg; k0 += 32) {
        const int nk = min(32, deg - k0);
        if (t < nk * 8) {
            const int kk = t >> 3;
            const int hh = t & 7;
            const int j = nbr[k0 + kk];
            float x = sS[hh] + g_sneigh[hh * N_NODES + j];
            x = (x > 0.0f) ? x : ALPHA * x;
            coef[kk][hh] = expf(x - sM[hh]) * sInvZ[hh];
        }
        __syncthreads();
#pragma unroll 4
        for (int kk = 0; kk < nk; kk++) {
            const int j = nbr[k0 + kk];
            const float c = coef[kk][myh];
            const float4 f = *reinterpret_cast<const float4*>(g_feats + (size_t)j * HC + 4 * t);
            acc.x = fmaf(c, f.x, acc.x);
            acc.y = fmaf(c, f.y, acc.y);
            acc.z = fmaf(c, f.z, acc.z);
            acc.w = fmaf(c, f.w, acc.w);
        }
        __syncthreads();
    }

    // epilogue: + bias, relu, store
    const int col = 4 * t;
    const float4 b4 = *reinterpret_cast<const float4*>(bias + col);
    acc.x = fmaxf(acc.x + b4.x, 0.0f);
    acc.y = fmaxf(acc.y + b4.y, 0.0f);
    acc.z = fmaxf(acc.z + b4.z, 0.0f);
    acc.w = fmaxf(acc.w + b4.w, 0.0f);
    *reinterpret_cast<float4*>(out + (size_t)i * HC + col) = acc;
}

// ---------------------------------------------------------------------------
extern "C" void kernel_launch(void* const* d_in, const int* in_sizes, int n_in,
                              void* d_out, int out_size) {
    const float* X       = (const float*)d_in[0];  // [4096, 512]
    const float* A       = (const float*)d_in[1];  // [4096, 4096]
    const float* W       = (const float*)d_in[2];  // [8, 512, 128]
    const float* a_self  = (const float*)d_in[3];  // [8, 128]
    const float* a_neigh = (const float*)d_in[4];  // [8, 128]
    const float* bias    = (const float*)d_in[5];  // [8, 128]
    float* out = (float*)d_out;                    // [4096, 1024]

    gemm_kernel<<<dim3(H_HEADS, N_NODES / 128), 256>>>(X, W);
    score_kernel<<<N_NODES, 256>>>(a_self, a_neigh);
    agg_kernel<<<N_NODES, 256>>>(A, bias, out);
}

// round 6
// speedup vs baseline: 1.5395x; 1.5395x over previous
#include <cuda_runtime.h>
#include <math.h>

#define N_NODES 4096
#define F_IN 512
#define H_HEADS 8
#define C_OUT 128
#define HC (H_HEADS * C_OUT)   // 1024
#define ALPHA 0.2f

// Scratch (allocation-free rule: __device__ globals)
__device__ float g_feats[N_NODES * HC];       // [n][h*128+c], 16 MB
__device__ float g_sself[H_HEADS * N_NODES];  // [h][n]
__device__ float g_sneigh[H_HEADS * N_NODES]; // [h][n]

// ---------------------------------------------------------------------------
// TF32 tensor-core GEMM: feats[m][h*128+c] = sum_f X[m][f] * W[h][f][c]
// grid (8, 32) = (head, m-tile). Block tile 128x128, BK=32, 256 threads.
// 8 warps as 2x4 -> warp tile 64x32, mma m16n8k8: 4x4 tiles per warp.
// ---------------------------------------------------------------------------
__device__ __forceinline__ unsigned f2tf32(float x) {
    unsigned u;
    asm("cvt.rna.tf32.f32 %0, %1;" : "=r"(u) : "f"(x));
    return u;
}

__device__ __forceinline__ void mma_tf32(float* c, const unsigned* a, const unsigned* b) {
    asm volatile(
        "mma.sync.aligned.m16n8k8.row.col.f32.tf32.tf32.f32 "
        "{%0,%1,%2,%3}, {%4,%5,%6,%7}, {%8,%9}, {%0,%1,%2,%3};"
        : "+f"(c[0]), "+f"(c[1]), "+f"(c[2]), "+f"(c[3])
        : "r"(a[0]), "r"(a[1]), "r"(a[2]), "r"(a[3]), "r"(b[0]), "r"(b[1]));
}

#define AS_STRIDE 36   // bank = (4r + c) % 32 -> conflict-free frag loads
#define BS_STRIDE 136  // bank = (8k + n) % 32 -> conflict-free frag loads

__global__ __launch_bounds__(256) void gemm_kernel(const float* __restrict__ X,
                                                   const float* __restrict__ W) {
    __shared__ unsigned As[128][AS_STRIDE];  // [m][k]
    __shared__ unsigned Bs[32][BS_STRIDE];   // [k][n]

    const int h  = blockIdx.x;
    const int m0 = blockIdx.y * 128;
    const float* Wh = W + (size_t)h * F_IN * C_OUT;

    const int t    = threadIdx.x;
    const int lane = t & 31;
    const int w    = t >> 5;
    const int warp_m = (w & 1) * 64;   // 0 or 64
    const int warp_n = (w >> 1) * 32;  // 0,32,64,96

    float acc[4][4][4];
#pragma unroll
    for (int mt = 0; mt < 4; mt++)
#pragma unroll
        for (int nt = 0; nt < 4; nt++)
#pragma unroll
            for (int q = 0; q < 4; q++) acc[mt][nt][q] = 0.0f;

    // Global-load indexing (4 float4 each for A and B per thread per chunk)
    const int a_row  = t >> 3;        // 0..31 (+32*p)
    const int a_col4 = (t & 7) * 4;   // 0..28
    const int b_row  = t >> 5;        // 0..7 (+8*p)
    const int b_col4 = (t & 31) * 4;  // 0..124

    float4 av[4], bv[4];
    // prefetch chunk 0
#pragma unroll
    for (int p = 0; p < 4; p++) {
        av[p] = *reinterpret_cast<const float4*>(
            X + (size_t)(m0 + a_row + p * 32) * F_IN + a_col4);
        bv[p] = *reinterpret_cast<const float4*>(
            Wh + (size_t)(b_row + p * 8) * C_OUT + b_col4);
    }

    for (int chunk = 0; chunk < F_IN / 32; chunk++) {
        __syncthreads();
#pragma unroll
        for (int p = 0; p < 4; p++) {
            unsigned* ad = &As[a_row + p * 32][a_col4];
            ad[0] = f2tf32(av[p].x); ad[1] = f2tf32(av[p].y);
            ad[2] = f2tf32(av[p].z); ad[3] = f2tf32(av[p].w);
            unsigned* bd = &Bs[b_row + p * 8][b_col4];
            bd[0] = f2tf32(bv[p].x); bd[1] = f2tf32(bv[p].y);
            bd[2] = f2tf32(bv[p].z); bd[3] = f2tf32(bv[p].w);
        }
        __syncthreads();

        if (chunk + 1 < F_IN / 32) {
            const int k0 = (chunk + 1) * 32;
#pragma unroll
            for (int p = 0; p < 4; p++) {
                av[p] = *reinterpret_cast<const float4*>(
                    X + (size_t)(m0 + a_row + p * 32) * F_IN + k0 + a_col4);
                bv[p] = *reinterpret_cast<const float4*>(
                    Wh + (size_t)(k0 + b_row + p * 8) * C_OUT + b_col4);
            }
        }

#pragma unroll
        for (int ks = 0; ks < 32; ks += 8) {
            unsigned afr[4][4], bfr[4][2];
            const int r0 = warp_m + (lane >> 2);
            const int cA = ks + (lane & 3);
#pragma unroll
            for (int mt = 0; mt < 4; mt++) {
                const int r = r0 + mt * 16;
                afr[mt][0] = As[r][cA];
                afr[mt][1] = As[r + 8][cA];
                afr[mt][2] = As[r][cA + 4];
                afr[mt][3] = As[r + 8][cA + 4];
            }
            const int rB = ks + (lane & 3);
            const int nB = warp_n + (lane >> 2);
#pragma unroll
            for (int nt = 0; nt < 4; nt++) {
                bfr[nt][0] = Bs[rB][nB + nt * 8];
                bfr[nt][1] = Bs[rB + 4][nB + nt * 8];
            }
#pragma unroll
            for (int mt = 0; mt < 4; mt++)
#pragma unroll
                for (int nt = 0; nt < 4; nt++)
                    mma_tf32(acc[mt][nt], afr[mt], bfr[nt]);
        }
    }

    // Epilogue: c0,c1 at (row, 2*(lane&3)); c2,c3 at (row+8)
    const int rbase = m0 + warp_m + (lane >> 2);
    const int cbase = h * C_OUT + warp_n + (lane & 3) * 2;
#pragma unroll
    for (int mt = 0; mt < 4; mt++) {
#pragma unroll
        for (int nt = 0; nt < 4; nt++) {
            const int r = rbase + mt * 16;
            const int c = cbase + nt * 8;
            float2 v0 = make_float2(acc[mt][nt][0], acc[mt][nt][1]);
            float2 v1 = make_float2(acc[mt][nt][2], acc[mt][nt][3]);
            *reinterpret_cast<float2*>(g_feats + (size_t)r * HC + c)       = v0;
            *reinterpret_cast<float2*>(g_feats + (size_t)(r + 8) * HC + c) = v1;
        }
    }
}

// ---------------------------------------------------------------------------
// Scores: s_self[h][n] = feats[n][h,:] . a_self[h,:]   (same for a_neigh)
// ---------------------------------------------------------------------------
__global__ __launch_bounds__(256) void score_kernel(const float* __restrict__ a_self,
                                                    const float* __restrict__ a_neigh) {
    const int n = blockIdx.x;
    const int h = threadIdx.x >> 5;
    const int lane = threadIdx.x & 31;
    const float* frow = g_feats + (size_t)n * HC + h * C_OUT;
    float ss = 0.0f, sn = 0.0f;
#pragma unroll
    for (int c = lane; c < C_OUT; c += 32) {
        float f = frow[c];
        ss = fmaf(f, a_self[h * C_OUT + c], ss);
        sn = fmaf(f, a_neigh[h * C_OUT + c], sn);
    }
#pragma unroll
    for (int o = 16; o > 0; o >>= 1) {
        ss += __shfl_xor_sync(0xffffffffu, ss, o);
        sn += __shfl_xor_sync(0xffffffffu, sn, o);
    }
    if (lane == 0) {
        g_sself[h * N_NODES + n]  = ss;
        g_sneigh[h * N_NODES + n] = sn;
    }
}

// ---------------------------------------------------------------------------
// Aggregation: one CTA per row i (unchanged, known-good).
// ---------------------------------------------------------------------------
__global__ __launch_bounds__(256) void agg_kernel(const float* __restrict__ A,
                                                  const float* __restrict__ bias,
                                                  float* __restrict__ out) {
    __shared__ int   nbr[N_NODES];
    __shared__ int   warp_cnt[8];
    __shared__ int   s_base;
    __shared__ float sM[H_HEADS], sInvZ[H_HEADS], sS[H_HEADS];
    __shared__ float coef[32][H_HEADS];

    const int i = blockIdx.x;
    const int t = threadIdx.x;
    const int lane = t & 31;
    const int w = t >> 5;

    const float* Arow = A + (size_t)i * N_NODES;

    if (t == 0) s_base = 0;
    __syncthreads();

    // ---- 1) ordered compaction (deterministic) ----
    for (int c0 = 0; c0 < N_NODES; c0 += 256) {
        const int col = c0 + t;
        const bool p = (Arow[col] != 0.0f);
        const unsigned bal = __ballot_sync(0xffffffffu, p);
        if (lane == 0) warp_cnt[w] = __popc(bal);
        __syncthreads();
        int woff = 0;
#pragma unroll
        for (int ww = 0; ww < 8; ww++)
            if (ww < w) woff += warp_cnt[ww];
        const int lpre = __popc(bal & ((1u << lane) - 1u));
        if (p) nbr[s_base + woff + lpre] = col;
        __syncthreads();
        if (t == 0) {
            int tot = 0;
#pragma unroll
            for (int ww = 0; ww < 8; ww++) tot += warp_cnt[ww];
            s_base += tot;
        }
        __syncthreads();
    }
    const int deg = s_base;  // >= 1 (self loop)

    // ---- 2) per-head softmax stats; warp w handles head w ----
    {
        const float ss = g_sself[w * N_NODES + i];
        float mx = -INFINITY;
        for (int k = lane; k < deg; k += 32)
            mx = fmaxf(mx, g_sneigh[w * N_NODES + nbr[k]]);
#pragma unroll
        for (int o = 16; o > 0; o >>= 1)
            mx = fmaxf(mx, __shfl_xor_sync(0xffffffffu, mx, o));
        float e = ss + mx;
        const float Mlogit = (e > 0.0f) ? e : ALPHA * e;  // leaky monotone -> true max logit

        float Z = 0.0f;
        for (int k = lane; k < deg; k += 32) {
            float x = ss + g_sneigh[w * N_NODES + nbr[k]];
            x = (x > 0.0f) ? x : ALPHA * x;
            Z += expf(x - Mlogit);
        }
#pragma unroll
        for (int o = 16; o > 0; o >>= 1)
            Z += __shfl_xor_sync(0xffffffffu, Z, o);
        if (lane == 0) {
            sM[w] = Mlogit;
            sInvZ[w] = 1.0f / Z;
            sS[w] = ss;
        }
    }
    __syncthreads();

    // ---- 3) gather-accumulate ----
    const int myh = t >> 5;
    float4 acc = make_float4(0.0f, 0.0f, 0.0f, 0.0f);

    for (int k0 = 0; k0 < deg; k0 += 32) {
        const int nk = min(32, deg - k0);
        if (t < nk * 8) {
            const int kk = t >> 3;
            const int hh = t & 7;
            const int j = nbr[k0 + kk];
            float x = sS[hh] + g_sneigh[hh * N_NODES + j];
            x = (x > 0.0f) ? x : ALPHA * x;
            coef[kk][hh] = expf(x - sM[hh]) * sInvZ[hh];
        }
        __syncthreads();
#pragma unroll 4
        for (int kk = 0; kk < nk; kk++) {
            const int j = nbr[k0 + kk];
            const float c = coef[kk][myh];
            const float4 f = *reinterpret_cast<const float4*>(g_feats + (size_t)j * HC + 4 * t);
            acc.x = fmaf(c, f.x, acc.x);
            acc.y = fmaf(c, f.y, acc.y);
            acc.z = fmaf(c, f.z, acc.z);
            acc.w = fmaf(c, f.w, acc.w);
        }
        __syncthreads();
    }

    // epilogue: + bias, relu, store
    const int col = 4 * t;
    const float4 b4 = *reinterpret_cast<const float4*>(bias + col);
    acc.x = fmaxf(acc.x + b4.x, 0.0f);
    acc.y = fmaxf(acc.y + b4.y, 0.0f);
    acc.z = fmaxf(acc.z + b4.z, 0.0f);
    acc.w = fmaxf(acc.w + b4.w, 0.0f);
    *reinterpret_cast<float4*>(out + (size_t)i * HC + col) = acc;
}

// ---------------------------------------------------------------------------
extern "C" void kernel_launch(void* const* d_in, const int* in_sizes, int n_in,
                              void* d_out, int out_size) {
    const float* X       = (const float*)d_in[0];  // [4096, 512]
    const float* A       = (const float*)d_in[1];  // [4096, 4096]
    const float* W       = (const float*)d_in[2];  // [8, 512, 128]
    const float* a_self  = (const float*)d_in[3];  // [8, 128]
    const float* a_neigh = (const float*)d_in[4];  // [8, 128]
    const float* bias    = (const float*)d_in[5];  // [8, 128]
    float* out = (float*)d_out;                    // [4096, 1024]

    gemm_kernel<<<dim3(H_HEADS, N_NODES / 128), 256>>>(X, W);
    score_kernel<<<N_NODES, 256>>>(a_self, a_neigh);
    agg_kernel<<<N_NODES, 256>>>(A, bias, out);
}

// round 7
// speedup vs baseline: 1.6200x; 1.0523x over previous
#include <cuda_runtime.h>
#include <cuda_fp16.h>
#include <math.h>

#define N_NODES 4096
#define F_IN 512
#define H_HEADS 8
#define C_OUT 128
#define HC (H_HEADS * C_OUT)   // 1024
#define ALPHA 0.2f

// Scratch (allocation-free rule: __device__ globals)
__device__ __half g_feats_h[N_NODES * HC];    // [n][h*128+c], 8 MB (L2-resident)
__device__ float  g_sself[H_HEADS * N_NODES]; // [h][n]
__device__ float  g_sneigh[H_HEADS * N_NODES];// [h][n]

// ---------------------------------------------------------------------------
// TF32 tensor-core GEMM + fused score epilogue.
// feats[m][h*128+c] = sum_f X[m][f] * W[h][f][c]  (stored as fp16)
// s_self[h][m] = feats[m][h,:] . a_self[h,:]      (fp32, reduced in-block)
// grid (8, 32) = (head, m-tile). Block tile 128x128, BK=32, 256 threads.
// 8 warps as 2x4 -> warp tile 64x32, mma m16n8k8: 4x4 tiles per warp.
// ---------------------------------------------------------------------------
__device__ __forceinline__ unsigned f2tf32(float x) {
    unsigned u;
    asm("cvt.rna.tf32.f32 %0, %1;" : "=r"(u) : "f"(x));
    return u;
}

__device__ __forceinline__ void mma_tf32(float* c, const unsigned* a, const unsigned* b) {
    asm volatile(
        "mma.sync.aligned.m16n8k8.row.col.f32.tf32.tf32.f32 "
        "{%0,%1,%2,%3}, {%4,%5,%6,%7}, {%8,%9}, {%0,%1,%2,%3};"
        : "+f"(c[0]), "+f"(c[1]), "+f"(c[2]), "+f"(c[3])
        : "r"(a[0]), "r"(a[1]), "r"(a[2]), "r"(a[3]), "r"(b[0]), "r"(b[1]));
}

#define AS_STRIDE 36   // bank = (4r + c) % 32 -> conflict-free frag loads
#define BS_STRIDE 136  // bank = (8k + n) % 32 -> conflict-free frag loads

__global__ __launch_bounds__(256) void gemm_kernel(const float* __restrict__ X,
                                                   const float* __restrict__ W,
                                                   const float* __restrict__ a_self,
                                                   const float* __restrict__ a_neigh) {
    __shared__ unsigned As[128][AS_STRIDE];  // [m][k]
    __shared__ unsigned Bs[32][BS_STRIDE];   // [k][n]
    __shared__ float sredS[4][128];          // per-warp_n-group score partials
    __shared__ float sredN[4][128];

    const int h  = blockIdx.x;
    const int m0 = blockIdx.y * 128;
    const float* Wh = W + (size_t)h * F_IN * C_OUT;

    const int t    = threadIdx.x;
    const int lane = t & 31;
    const int w    = t >> 5;
    const int warp_m = (w & 1) * 64;   // 0 or 64
    const int warp_n = (w >> 1) * 32;  // 0,32,64,96

    float acc[4][4][4];
#pragma unroll
    for (int mt = 0; mt < 4; mt++)
#pragma unroll
        for (int nt = 0; nt < 4; nt++)
#pragma unroll
            for (int q = 0; q < 4; q++) acc[mt][nt][q] = 0.0f;

    // Global-load indexing (4 float4 each for A and B per thread per chunk)
    const int a_row  = t >> 3;        // 0..31 (+32*p)
    const int a_col4 = (t & 7) * 4;   // 0..28
    const int b_row  = t >> 5;        // 0..7 (+8*p)
    const int b_col4 = (t & 31) * 4;  // 0..124

    float4 av[4], bv[4];
    // prefetch chunk 0
#pragma unroll
    for (int p = 0; p < 4; p++) {
        av[p] = *reinterpret_cast<const float4*>(
            X + (size_t)(m0 + a_row + p * 32) * F_IN + a_col4);
        bv[p] = *reinterpret_cast<const float4*>(
            Wh + (size_t)(b_row + p * 8) * C_OUT + b_col4);
    }

    for (int chunk = 0; chunk < F_IN / 32; chunk++) {
        __syncthreads();
#pragma unroll
        for (int p = 0; p < 4; p++) {
            unsigned* ad = &As[a_row + p * 32][a_col4];
            ad[0] = f2tf32(av[p].x); ad[1] = f2tf32(av[p].y);
            ad[2] = f2tf32(av[p].z); ad[3] = f2tf32(av[p].w);
            unsigned* bd = &Bs[b_row + p * 8][b_col4];
            bd[0] = f2tf32(bv[p].x); bd[1] = f2tf32(bv[p].y);
            bd[2] = f2tf32(bv[p].z); bd[3] = f2tf32(bv[p].w);
        }
        __syncthreads();

        if (chunk + 1 < F_IN / 32) {
            const int k0 = (chunk + 1) * 32;
#pragma unroll
            for (int p = 0; p < 4; p++) {
                av[p] = *reinterpret_cast<const float4*>(
                    X + (size_t)(m0 + a_row + p * 32) * F_IN + k0 + a_col4);
                bv[p] = *reinterpret_cast<const float4*>(
                    Wh + (size_t)(k0 + b_row + p * 8) * C_OUT + b_col4);
            }
        }

#pragma unroll
        for (int ks = 0; ks < 32; ks += 8) {
            unsigned afr[4][4], bfr[4][2];
            const int r0 = warp_m + (lane >> 2);
            const int cA = ks + (lane & 3);
#pragma unroll
            for (int mt = 0; mt < 4; mt++) {
                const int r = r0 + mt * 16;
                afr[mt][0] = As[r][cA];
                afr[mt][1] = As[r + 8][cA];
                afr[mt][2] = As[r][cA + 4];
                afr[mt][3] = As[r + 8][cA + 4];
            }
            const int rB = ks + (lane & 3);
            const int nB = warp_n + (lane >> 2);
#pragma unroll
            for (int nt = 0; nt < 4; nt++) {
                bfr[nt][0] = Bs[rB][nB + nt * 8];
                bfr[nt][1] = Bs[rB + 4][nB + nt * 8];
            }
#pragma unroll
            for (int mt = 0; mt < 4; mt++)
#pragma unroll
                for (int nt = 0; nt < 4; nt++)
                    mma_tf32(acc[mt][nt], afr[mt], bfr[nt]);
        }
    }

    // ---- Epilogue: fp16 feats store + fused score reduction ----
    // Thread owns rows: warp_m + (lane>>2) + mt*16 + p*8  (p=0 -> acc[..][0,1], p=1 -> acc[..][2,3])
    //            cols:  warp_n + (lane&3)*2 + nt*8 + u    (u=0,1)
    const int rloc  = warp_m + (lane >> 2);            // local row base
    const int cloc  = warp_n + (lane & 3) * 2;         // local col base
    const int cbase = h * C_OUT + cloc;

    // per-thread attention-vector values for its 8 columns
    float asf[4][2], anf[4][2];
#pragma unroll
    for (int nt = 0; nt < 4; nt++) {
        float2 s2 = *reinterpret_cast<const float2*>(a_self  + h * C_OUT + cloc + nt * 8);
        float2 n2 = *reinterpret_cast<const float2*>(a_neigh + h * C_OUT + cloc + nt * 8);
        asf[nt][0] = s2.x; asf[nt][1] = s2.y;
        anf[nt][0] = n2.x; anf[nt][1] = n2.y;
    }

#pragma unroll
    for (int mt = 0; mt < 4; mt++) {
#pragma unroll
        for (int p = 0; p < 2; p++) {
            const int r = m0 + rloc + mt * 16 + p * 8;
            float ssp = 0.0f, snp = 0.0f;
#pragma unroll
            for (int nt = 0; nt < 4; nt++) {
                const float v0 = acc[mt][nt][2 * p];
                const float v1 = acc[mt][nt][2 * p + 1];
                ssp = fmaf(v0, asf[nt][0], ssp);
                ssp = fmaf(v1, asf[nt][1], ssp);
                snp = fmaf(v0, anf[nt][0], snp);
                snp = fmaf(v1, anf[nt][1], snp);
                // fp16 store (2 adjacent cols)
                __half2 hv = __floats2half2_rn(v0, v1);
                *reinterpret_cast<__half2*>(g_feats_h + (size_t)r * HC + cbase + nt * 8) = hv;
            }
            // reduce over lane&3 (covers all 32 cols of this warp)
            ssp += __shfl_xor_sync(0xffffffffu, ssp, 1);
            ssp += __shfl_xor_sync(0xffffffffu, ssp, 2);
            snp += __shfl_xor_sync(0xffffffffu, snp, 1);
            snp += __shfl_xor_sync(0xffffffffu, snp, 2);
            if ((lane & 3) == 0) {
                const int rl = rloc + mt * 16 + p * 8;  // 0..127
                sredS[w >> 1][rl] = ssp;
                sredN[w >> 1][rl] = snp;
            }
        }
    }
    __syncthreads();
    if (t < 128) {
        float ss = sredS[0][t] + sredS[1][t] + sredS[2][t] + sredS[3][t];
        float sn = sredN[0][t] + sredN[1][t] + sredN[2][t] + sredN[3][t];
        g_sself[h * N_NODES + m0 + t]  = ss;
        g_sneigh[h * N_NODES + m0 + t] = sn;
    }
}

// ---------------------------------------------------------------------------
// Aggregation: one CTA per row i. fp16 feature gather, fp32 accumulate.
// ---------------------------------------------------------------------------
__global__ __launch_bounds__(256) void agg_kernel(const float* __restrict__ A,
                                                  const float* __restrict__ bias,
                                                  float* __restrict__ out) {
    __shared__ int   nbr[N_NODES];
    __shared__ int   warp_cnt[8];
    __shared__ int   s_base;
    __shared__ float sM[H_HEADS], sInvZ[H_HEADS], sS[H_HEADS];
    __shared__ float coef[32][H_HEADS];

    const int i = blockIdx.x;
    const int t = threadIdx.x;
    const int lane = t & 31;
    const int w = t >> 5;

    const float* Arow = A + (size_t)i * N_NODES;

    if (t == 0) s_base = 0;
    __syncthreads();

    // ---- 1) ordered compaction (deterministic) ----
    for (int c0 = 0; c0 < N_NODES; c0 += 256) {
        const int col = c0 + t;
        const bool p = (Arow[col] != 0.0f);
        const unsigned bal = __ballot_sync(0xffffffffu, p);
        if (lane == 0) warp_cnt[w] = __popc(bal);
        __syncthreads();
        int woff = 0;
#pragma unroll
        for (int ww = 0; ww < 8; ww++)
            if (ww < w) woff += warp_cnt[ww];
        const int lpre = __popc(bal & ((1u << lane) - 1u));
        if (p) nbr[s_base + woff + lpre] = col;
        __syncthreads();
        if (t == 0) {
            int tot = 0;
#pragma unroll
            for (int ww = 0; ww < 8; ww++) tot += warp_cnt[ww];
            s_base += tot;
        }
        __syncthreads();
    }
    const int deg = s_base;  // >= 1 (self loop)

    // ---- 2) per-head softmax stats; warp w handles head w ----
    {
        const float ss = g_sself[w * N_NODES + i];
        float mx = -INFINITY;
        for (int k = lane; k < deg; k += 32)
            mx = fmaxf(mx, g_sneigh[w * N_NODES + nbr[k]]);
#pragma unroll
        for (int o = 16; o > 0; o >>= 1)
            mx = fmaxf(mx, __shfl_xor_sync(0xffffffffu, mx, o));
        float e = ss + mx;
        const float Mlogit = (e > 0.0f) ? e : ALPHA * e;  // leaky monotone -> true max logit

        float Z = 0.0f;
        for (int k = lane; k < deg; k += 32) {
            float x = ss + g_sneigh[w * N_NODES + nbr[k]];
            x = (x > 0.0f) ? x : ALPHA * x;
            Z += expf(x - Mlogit);
        }
#pragma unroll
        for (int o = 16; o > 0; o >>= 1)
            Z += __shfl_xor_sync(0xffffffffu, Z, o);
        if (lane == 0) {
            sM[w] = Mlogit;
            sInvZ[w] = 1.0f / Z;
            sS[w] = ss;
        }
    }
    __syncthreads();

    // ---- 3) gather-accumulate (fp16 rows, fp32 acc) ----
    const int myh = t >> 5;  // cols 4t..4t+3 all lie in head t/32
    float4 acc = make_float4(0.0f, 0.0f, 0.0f, 0.0f);

    for (int k0 = 0; k0 < deg; k0 += 32) {
        const int nk = min(32, deg - k0);
        if (t < nk * 8) {
            const int kk = t >> 3;
            const int hh = t & 7;
            const int j = nbr[k0 + kk];
            float x = sS[hh] + g_sneigh[hh * N_NODES + j];
            x = (x > 0.0f) ? x : ALPHA * x;
            coef[kk][hh] = expf(x - sM[hh]) * sInvZ[hh];
        }
        __syncthreads();
#pragma unroll 4
        for (int kk = 0; kk < nk; kk++) {
            const int j = nbr[k0 + kk];
            const float c = coef[kk][myh];
            // 4 halves = 8 bytes, coalesced across the CTA
            const uint2 v = *reinterpret_cast<const uint2*>(
                g_feats_h + (size_t)j * HC + 4 * t);
            const float2 f0 = __half22float2(*reinterpret_cast<const __half2*>(&v.x));
            const float2 f1 = __half22float2(*reinterpret_cast<const __half2*>(&v.y));
            acc.x = fmaf(c, f0.x, acc.x);
            acc.y = fmaf(c, f0.y, acc.y);
            acc.z = fmaf(c, f1.x, acc.z);
            acc.w = fmaf(c, f1.y, acc.w);
        }
        __syncthreads();
    }

    // epilogue: + bias, relu, store
    const int col = 4 * t;
    const float4 b4 = *reinterpret_cast<const float4*>(bias + col);
    acc.x = fmaxf(acc.x + b4.x, 0.0f);
    acc.y = fmaxf(acc.y + b4.y, 0.0f);
    acc.z = fmaxf(acc.z + b4.z, 0.0f);
    acc.w = fmaxf(acc.w + b4.w, 0.0f);
    *reinterpret_cast<float4*>(out + (size_t)i * HC + col) = acc;
}

// ---------------------------------------------------------------------------
extern "C" void kernel_launch(void* const* d_in, const int* in_sizes, int n_in,
                              void* d_out, int out_size) {
    const float* X       = (const float*)d_in[0];  // [4096, 512]
    const float* A       = (const float*)d_in[1];  // [4096, 4096]
    const float* W       = (const float*)d_in[2];  // [8, 512, 128]
    const float* a_self  = (const float*)d_in[3];  // [8, 128]
    const float* a_neigh = (const float*)d_in[4];  // [8, 128]
    const float* bias    = (const float*)d_in[5];  // [8, 128]
    float* out = (float*)d_out;                    // [4096, 1024]

    gemm_kernel<<<dim3(H_HEADS, N_NODES / 128), 256>>>(X, W, a_self, a_neigh);
    agg_kernel<<<N_NODES, 256>>>(A, bias, out);
}

// round 8
// speedup vs baseline: 1.7707x; 1.0930x over previous
#include <cuda_runtime.h>
#include <cuda_fp16.h>
#include <math.h>

#define N_NODES 4096
#define F_IN 512
#define H_HEADS 8
#define C_OUT 128
#define HC (H_HEADS * C_OUT)   // 1024
#define ALPHA 0.2f

// Scratch (allocation-free rule: __device__ globals)
__device__ __half g_feats_h[N_NODES * HC];    // [n][h*128+c], 8 MB (L2-resident)
__device__ float  g_sself[H_HEADS * N_NODES]; // [h][n]
__device__ float  g_sneigh[H_HEADS * N_NODES];// [h][n]

// ---------------------------------------------------------------------------
// TF32 tensor-core GEMM + fused score epilogue (unchanged from R7).
// ---------------------------------------------------------------------------
__device__ __forceinline__ unsigned f2tf32(float x) {
    unsigned u;
    asm("cvt.rna.tf32.f32 %0, %1;" : "=r"(u) : "f"(x));
    return u;
}

__device__ __forceinline__ void mma_tf32(float* c, const unsigned* a, const unsigned* b) {
    asm volatile(
        "mma.sync.aligned.m16n8k8.row.col.f32.tf32.tf32.f32 "
        "{%0,%1,%2,%3}, {%4,%5,%6,%7}, {%8,%9}, {%0,%1,%2,%3};"
        : "+f"(c[0]), "+f"(c[1]), "+f"(c[2]), "+f"(c[3])
        : "r"(a[0]), "r"(a[1]), "r"(a[2]), "r"(a[3]), "r"(b[0]), "r"(b[1]));
}

#define AS_STRIDE 36   // bank = (4r + c) % 32 -> conflict-free frag loads
#define BS_STRIDE 136  // bank = (8k + n) % 32 -> conflict-free frag loads

__global__ __launch_bounds__(256) void gemm_kernel(const float* __restrict__ X,
                                                   const float* __restrict__ W,
                                                   const float* __restrict__ a_self,
                                                   const float* __restrict__ a_neigh) {
    __shared__ unsigned As[128][AS_STRIDE];  // [m][k]
    __shared__ unsigned Bs[32][BS_STRIDE];   // [k][n]
    __shared__ float sredS[4][128];
    __shared__ float sredN[4][128];

    const int h  = blockIdx.x;
    const int m0 = blockIdx.y * 128;
    const float* Wh = W + (size_t)h * F_IN * C_OUT;

    const int t    = threadIdx.x;
    const int lane = t & 31;
    const int w    = t >> 5;
    const int warp_m = (w & 1) * 64;
    const int warp_n = (w >> 1) * 32;

    float acc[4][4][4];
#pragma unroll
    for (int mt = 0; mt < 4; mt++)
#pragma unroll
        for (int nt = 0; nt < 4; nt++)
#pragma unroll
            for (int q = 0; q < 4; q++) acc[mt][nt][q] = 0.0f;

    const int a_row  = t >> 3;
    const int a_col4 = (t & 7) * 4;
    const int b_row  = t >> 5;
    const int b_col4 = (t & 31) * 4;

    float4 av[4], bv[4];
#pragma unroll
    for (int p = 0; p < 4; p++) {
        av[p] = *reinterpret_cast<const float4*>(
            X + (size_t)(m0 + a_row + p * 32) * F_IN + a_col4);
        bv[p] = *reinterpret_cast<const float4*>(
            Wh + (size_t)(b_row + p * 8) * C_OUT + b_col4);
    }

    for (int chunk = 0; chunk < F_IN / 32; chunk++) {
        __syncthreads();
#pragma unroll
        for (int p = 0; p < 4; p++) {
            unsigned* ad = &As[a_row + p * 32][a_col4];
            ad[0] = f2tf32(av[p].x); ad[1] = f2tf32(av[p].y);
            ad[2] = f2tf32(av[p].z); ad[3] = f2tf32(av[p].w);
            unsigned* bd = &Bs[b_row + p * 8][b_col4];
            bd[0] = f2tf32(bv[p].x); bd[1] = f2tf32(bv[p].y);
            bd[2] = f2tf32(bv[p].z); bd[3] = f2tf32(bv[p].w);
        }
        __syncthreads();

        if (chunk + 1 < F_IN / 32) {
            const int k0 = (chunk + 1) * 32;
#pragma unroll
            for (int p = 0; p < 4; p++) {
                av[p] = *reinterpret_cast<const float4*>(
                    X + (size_t)(m0 + a_row + p * 32) * F_IN + k0 + a_col4);
                bv[p] = *reinterpret_cast<const float4*>(
                    Wh + (size_t)(k0 + b_row + p * 8) * C_OUT + b_col4);
            }
        }

#pragma unroll
        for (int ks = 0; ks < 32; ks += 8) {
            unsigned afr[4][4], bfr[4][2];
            const int r0 = warp_m + (lane >> 2);
            const int cA = ks + (lane & 3);
#pragma unroll
            for (int mt = 0; mt < 4; mt++) {
                const int r = r0 + mt * 16;
                afr[mt][0] = As[r][cA];
                afr[mt][1] = As[r + 8][cA];
                afr[mt][2] = As[r][cA + 4];
                afr[mt][3] = As[r + 8][cA + 4];
            }
            const int rB = ks + (lane & 3);
            const int nB = warp_n + (lane >> 2);
#pragma unroll
            for (int nt = 0; nt < 4; nt++) {
                bfr[nt][0] = Bs[rB][nB + nt * 8];
                bfr[nt][1] = Bs[rB + 4][nB + nt * 8];
            }
#pragma unroll
            for (int mt = 0; mt < 4; mt++)
#pragma unroll
                for (int nt = 0; nt < 4; nt++)
                    mma_tf32(acc[mt][nt], afr[mt], bfr[nt]);
        }
    }

    // Epilogue: fp16 feats store + fused score reduction
    const int rloc  = warp_m + (lane >> 2);
    const int cloc  = warp_n + (lane & 3) * 2;
    const int cbase = h * C_OUT + cloc;

    float asf[4][2], anf[4][2];
#pragma unroll
    for (int nt = 0; nt < 4; nt++) {
        float2 s2 = *reinterpret_cast<const float2*>(a_self  + h * C_OUT + cloc + nt * 8);
        float2 n2 = *reinterpret_cast<const float2*>(a_neigh + h * C_OUT + cloc + nt * 8);
        asf[nt][0] = s2.x; asf[nt][1] = s2.y;
        anf[nt][0] = n2.x; anf[nt][1] = n2.y;
    }

#pragma unroll
    for (int mt = 0; mt < 4; mt++) {
#pragma unroll
        for (int p = 0; p < 2; p++) {
            const int r = m0 + rloc + mt * 16 + p * 8;
            float ssp = 0.0f, snp = 0.0f;
#pragma unroll
            for (int nt = 0; nt < 4; nt++) {
                const float v0 = acc[mt][nt][2 * p];
                const float v1 = acc[mt][nt][2 * p + 1];
                ssp = fmaf(v0, asf[nt][0], ssp);
                ssp = fmaf(v1, asf[nt][1], ssp);
                snp = fmaf(v0, anf[nt][0], snp);
                snp = fmaf(v1, anf[nt][1], snp);
                __half2 hv = __floats2half2_rn(v0, v1);
                *reinterpret_cast<__half2*>(g_feats_h + (size_t)r * HC + cbase + nt * 8) = hv;
            }
            ssp += __shfl_xor_sync(0xffffffffu, ssp, 1);
            ssp += __shfl_xor_sync(0xffffffffu, ssp, 2);
            snp += __shfl_xor_sync(0xffffffffu, snp, 1);
            snp += __shfl_xor_sync(0xffffffffu, snp, 2);
            if ((lane & 3) == 0) {
                const int rl = rloc + mt * 16 + p * 8;
                sredS[w >> 1][rl] = ssp;
                sredN[w >> 1][rl] = snp;
            }
        }
    }
    __syncthreads();
    if (t < 128) {
        float ss = sredS[0][t] + sredS[1][t] + sredS[2][t] + sredS[3][t];
        float sn = sredN[0][t] + sredN[1][t] + sredN[2][t] + sredN[3][t];
        g_sself[h * N_NODES + m0 + t]  = ss;
        g_sneigh[h * N_NODES + m0 + t] = sn;
    }
}

// ---------------------------------------------------------------------------
// Aggregation (rewritten): one CTA per row i.
//  1) per-warp segment compaction, MLP=16, barrier-free; 2-sync global compact
//  2) per-head softmax stats (warp = head), __expf
//  3) 64-neighbor chunks: coef table, then paired gather: each thread loads
//     uint4 (8 halves / 8 cols); thread halves take alternating neighbors.
// ---------------------------------------------------------------------------
__global__ __launch_bounds__(256) void agg_kernel(const float* __restrict__ A,
                                                  const float* __restrict__ bias,
                                                  float* __restrict__ out) {
    __shared__ int   nbr[N_NODES];      // 16 KB
    __shared__ int   warp_cnt[8];
    __shared__ float sM[H_HEADS], sInvZ[H_HEADS], sS[H_HEADS];
    __shared__ float coef[64][H_HEADS]; // 2 KB
    __shared__ float red[128][8];       // 4 KB

    const int i    = blockIdx.x;
    const int t    = threadIdx.x;
    const int lane = t & 31;
    const int w    = t >> 5;

    const float* Arow = A + (size_t)i * N_NODES;

    // ---- 1) per-warp compaction into private segment (no block syncs) ----
    {
        float vals[16];
        const int cbase0 = w * 512 + lane;
#pragma unroll
        for (int b = 0; b < 16; b++) vals[b] = Arow[cbase0 + b * 32];  // MLP=16
        int wcnt = 0;
        const unsigned lmask = (1u << lane) - 1u;
#pragma unroll
        for (int b = 0; b < 16; b++) {
            const bool p = (vals[b] != 0.0f);
            const unsigned bal = __ballot_sync(0xffffffffu, p);
            if (p) nbr[w * 512 + wcnt + __popc(bal & lmask)] = cbase0 + b * 32;
            wcnt += __popc(bal);
        }
        if (lane == 0) warp_cnt[w] = wcnt;
    }
    __syncthreads();

    int pref[9];
    pref[0] = 0;
#pragma unroll
    for (int ww = 0; ww < 8; ww++) pref[ww + 1] = pref[ww] + warp_cnt[ww];
    const int deg = pref[8];  // >= 1 (self loop)

    // in-place segment compaction: read-to-regs, sync, write
    {
        int v[16];
#pragma unroll
        for (int c = 0; c < 16; c++) {
            const int idx = t + c * 256;
            if (idx < deg) {
                int seg = 0;
#pragma unroll
                for (int ww = 1; ww < 8; ww++)
                    if (idx >= pref[ww]) seg = ww;
                v[c] = nbr[seg * 512 + idx - pref[seg]];
            }
        }
        __syncthreads();
#pragma unroll
        for (int c = 0; c < 16; c++) {
            const int idx = t + c * 256;
            if (idx < deg) nbr[idx] = v[c];
        }
    }
    __syncthreads();

    // ---- 2) per-head softmax stats; warp w handles head w ----
    {
        const float ss = g_sself[w * N_NODES + i];
        const float* snh = g_sneigh + (size_t)w * N_NODES;
        float mx = -INFINITY;
#pragma unroll 4
        for (int k = lane; k < deg; k += 32)
            mx = fmaxf(mx, snh[nbr[k]]);
#pragma unroll
        for (int o = 16; o > 0; o >>= 1)
            mx = fmaxf(mx, __shfl_xor_sync(0xffffffffu, mx, o));
        float e = ss + mx;
        const float Mlogit = (e > 0.0f) ? e : ALPHA * e;  // leaky monotone

        float Z = 0.0f;
#pragma unroll 4
        for (int k = lane; k < deg; k += 32) {
            float x = ss + snh[nbr[k]];
            x = (x > 0.0f) ? x : ALPHA * x;
            Z += __expf(x - Mlogit);
        }
#pragma unroll
        for (int o = 16; o > 0; o >>= 1)
            Z += __shfl_xor_sync(0xffffffffu, Z, o);
        if (lane == 0) {
            sM[w] = Mlogit;
            sInvZ[w] = 1.0f / Z;
            sS[w] = ss;
        }
    }
    __syncthreads();

    // ---- 3) chunked coef + paired uint4 gather ----
    const int hh_t    = (t & 127) >> 4;     // head of my 8 columns
    const int colbase = (t & 127) * 8;      // my 8 columns
    const int ksel    = t >> 7;             // which neighbor of each pair
    float acc[8];
#pragma unroll
    for (int q = 0; q < 8; q++) acc[q] = 0.0f;

    for (int k0 = 0; k0 < deg; k0 += 64) {
        const int nk = min(64, deg - k0);
        // coef table: 512 slots, 2 per thread
#pragma unroll
        for (int r = 0; r < 2; r++) {
            const int s  = t + 256 * r;
            const int kk = s >> 3;
            const int hh = s & 7;
            if (kk < nk) {
                const int j = nbr[k0 + kk];
                float x = sS[hh] + g_sneigh[hh * N_NODES + j];
                x = (x > 0.0f) ? x : ALPHA * x;
                coef[kk][hh] = __expf(x - sM[hh]) * sInvZ[hh];
            }
        }
        __syncthreads();

        for (int m = 0; m < nk; m += 4) {
            const int k1 = m + ksel;
            const int k2 = m + 2 + ksel;
            const bool p1 = (k1 < nk);
            const bool p2 = (k2 < nk);
            const int j1 = p1 ? nbr[k0 + k1] : 0;
            const int j2 = p2 ? nbr[k0 + k2] : 0;
            uint4 v1 = make_uint4(0, 0, 0, 0), v2 = make_uint4(0, 0, 0, 0);
            if (p1) v1 = *reinterpret_cast<const uint4*>(g_feats_h + (size_t)j1 * HC + colbase);
            if (p2) v2 = *reinterpret_cast<const uint4*>(g_feats_h + (size_t)j2 * HC + colbase);
            const float c1 = p1 ? coef[k1][hh_t] : 0.0f;
            const float c2 = p2 ? coef[k2][hh_t] : 0.0f;
            {
                const float2 f0 = __half22float2(*reinterpret_cast<const __half2*>(&v1.x));
                const float2 f1 = __half22float2(*reinterpret_cast<const __half2*>(&v1.y));
                const float2 f2 = __half22float2(*reinterpret_cast<const __half2*>(&v1.z));
                const float2 f3 = __half22float2(*reinterpret_cast<const __half2*>(&v1.w));
                acc[0] = fmaf(c1, f0.x, acc[0]); acc[1] = fmaf(c1, f0.y, acc[1]);
                acc[2] = fmaf(c1, f1.x, acc[2]); acc[3] = fmaf(c1, f1.y, acc[3]);
                acc[4] = fmaf(c1, f2.x, acc[4]); acc[5] = fmaf(c1, f2.y, acc[5]);
                acc[6] = fmaf(c1, f3.x, acc[6]); acc[7] = fmaf(c1, f3.y, acc[7]);
            }
            {
                const float2 f0 = __half22float2(*reinterpret_cast<const __half2*>(&v2.x));
                const float2 f1 = __half22float2(*reinterpret_cast<const __half2*>(&v2.y));
                const float2 f2 = __half22float2(*reinterpret_cast<const __half2*>(&v2.z));
                const float2 f3 = __half22float2(*reinterpret_cast<const __half2*>(&v2.w));
                acc[0] = fmaf(c2, f0.x, acc[0]); acc[1] = fmaf(c2, f0.y, acc[1]);
                acc[2] = fmaf(c2, f1.x, acc[2]); acc[3] = fmaf(c2, f1.y, acc[3]);
                acc[4] = fmaf(c2, f2.x, acc[4]); acc[5] = fmaf(c2, f2.y, acc[5]);
                acc[6] = fmaf(c2, f3.x, acc[6]); acc[7] = fmaf(c2, f3.y, acc[7]);
            }
        }
        __syncthreads();
    }

    // cross-half reduction + epilogue
    if (t >= 128) {
#pragma unroll
        for (int q = 0; q < 8; q++) red[t - 128][q] = acc[q];
    }
    __syncthreads();
    if (t < 128) {
        float4 b0 = *reinterpret_cast<const float4*>(bias + colbase);
        float4 b1 = *reinterpret_cast<const float4*>(bias + colbase + 4);
        float o0 = fmaxf(acc[0] + red[t][0] + b0.x, 0.0f);
        float o1 = fmaxf(acc[1] + red[t][1] + b0.y, 0.0f);
        float o2 = fmaxf(acc[2] + red[t][2] + b0.z, 0.0f);
        float o3 = fmaxf(acc[3] + red[t][3] + b0.w, 0.0f);
        float o4 = fmaxf(acc[4] + red[t][4] + b1.x, 0.0f);
        float o5 = fmaxf(acc[5] + red[t][5] + b1.y, 0.0f);
        float o6 = fmaxf(acc[6] + red[t][6] + b1.z, 0.0f);
        float o7 = fmaxf(acc[7] + red[t][7] + b1.w, 0.0f);
        float* dst = out + (size_t)i * HC + colbase;
        *reinterpret_cast<float4*>(dst)     = make_float4(o0, o1, o2, o3);
        *reinterpret_cast<float4*>(dst + 4) = make_float4(o4, o5, o6, o7);
    }
}

// ---------------------------------------------------------------------------
extern "C" void kernel_launch(void* const* d_in, const int* in_sizes, int n_in,
                              void* d_out, int out_size) {
    const float* X       = (const float*)d_in[0];  // [4096, 512]
    const float* A       = (const float*)d_in[1];  // [4096, 4096]
    const float* W       = (const float*)d_in[2];  // [8, 512, 128]
    const float* a_self  = (const float*)d_in[3];  // [8, 128]
    const float* a_neigh = (const float*)d_in[4];  // [8, 128]
    const float* bias    = (const float*)d_in[5];  // [8, 128]
    float* out = (float*)d_out;                    // [4096, 1024]

    gemm_kernel<<<dim3(H_HEADS, N_NODES / 128), 256>>>(X, W, a_self, a_neigh);
    agg_kernel<<<N_NODES, 256>>>(A, bias, out);
}